// round 1
// baseline (speedup 1.0000x reference)
#include <cuda_runtime.h>
#include <math.h>

// Problem constants
#define BB   32
#define NN   64
#define NH   16
#define RR   1024
#define REP  1024
#define RH   512
#define MM   1008
#define NCLS 117

// Output layout offsets (floats)
#define OFF_BH  66060288L
#define OFF_BO  66189312L
#define OFF_PR  66318336L

// ---------------- scratch (device globals; no allocation allowed) ------------
__device__ float g_encA[BB * NN * RR];
__device__ float g_encB[BB * NN * RR];
__device__ float g_U [BB * NN * REP];
__device__ float g_V [BB * NN * REP];
__device__ float g_O [BB * NN * REP];
__device__ float g_mh[BB * NH * REP];
__device__ float g_eh[BB * NH * RR];
__device__ float g_S [BB * NH * REP];
__device__ float g_mo[BB * NN * REP];
__device__ float g_A [BB * NH * NN];

// ---------------- generic batched GEMM: C = act(A @ W + bias) ----------------
// A may be a K-concat of two row-major matrices A1 [M,K1] and A2 [M,K-K1].
// W is row-major [K,1024]. C row-major [M,1024]. grid: (16, 1, B). 256 thr.
#define BKK 16
__global__ __launch_bounds__(256) void gemm64(
    const float* __restrict__ A1, int K1, const float* __restrict__ A2,
    long sA1, long sA2,
    const float* __restrict__ W, const float* __restrict__ bias,
    float* __restrict__ C, long sC, int Mrows, int Ktot, int do_relu)
{
    __shared__ __align__(16) float As[BKK][64];
    __shared__ __align__(16) float Bs[BKK][64];

    const int b  = blockIdx.z;
    const int n0 = blockIdx.x * 64;
    const int t  = threadIdx.x;
    const int tr = t >> 4;          // 0..15 -> rows 4*tr..4*tr+3
    const int tc = t & 15;          // 0..15 -> cols 4*tc..4*tc+3
    const int lm  = t >> 2;         // A-load row 0..63
    const int lk4 = (t & 3) * 4;    // A-load col base
    const int bk  = t >> 4;         // B-load row 0..15
    const int bn4 = (t & 15) * 4;   // B-load col base

    const float* A1b = A1 + (long)b * sA1;
    const float* A2b = A2 ? (A2 + (long)b * sA2) : (const float*)0;
    const int K2 = Ktot - K1;

    float acc[4][4];
#pragma unroll
    for (int i = 0; i < 4; i++)
#pragma unroll
        for (int j = 0; j < 4; j++) acc[i][j] = 0.f;

    for (int k0 = 0; k0 < Ktot; k0 += BKK) {
        // ---- A tile (transposed to [k][m]) ----
        float4 av = make_float4(0.f, 0.f, 0.f, 0.f);
        if (lm < Mrows) {
            if (k0 < K1) av = *(const float4*)(A1b + (long)lm * K1 + (k0 + lk4));
            else         av = *(const float4*)(A2b + (long)lm * K2 + (k0 - K1 + lk4));
        }
        As[lk4 + 0][lm] = av.x; As[lk4 + 1][lm] = av.y;
        As[lk4 + 2][lm] = av.z; As[lk4 + 3][lm] = av.w;
        // ---- B tile ----
        *(float4*)&Bs[bk][bn4] = *(const float4*)(W + (long)(k0 + bk) * 1024 + n0 + bn4);
        __syncthreads();

#pragma unroll
        for (int kk = 0; kk < BKK; kk++) {
            float4 a  = *(const float4*)&As[kk][4 * tr];
            float4 w4 = *(const float4*)&Bs[kk][4 * tc];
            acc[0][0] += a.x * w4.x; acc[0][1] += a.x * w4.y; acc[0][2] += a.x * w4.z; acc[0][3] += a.x * w4.w;
            acc[1][0] += a.y * w4.x; acc[1][1] += a.y * w4.y; acc[1][2] += a.y * w4.z; acc[1][3] += a.y * w4.w;
            acc[2][0] += a.z * w4.x; acc[2][1] += a.z * w4.y; acc[2][2] += a.z * w4.z; acc[2][3] += a.z * w4.w;
            acc[3][0] += a.w * w4.x; acc[3][1] += a.w * w4.y; acc[3][2] += a.w * w4.z; acc[3][3] += a.w * w4.w;
        }
        __syncthreads();
    }

    const int col = n0 + 4 * tc;
    float4 bv = make_float4(0.f, 0.f, 0.f, 0.f);
    if (bias) bv = *(const float4*)(bias + col);
#pragma unroll
    for (int i = 0; i < 4; i++) {
        int row = 4 * tr + i;
        if (row < Mrows) {
            float4 v;
            v.x = acc[i][0] + bv.x; v.y = acc[i][1] + bv.y;
            v.z = acc[i][2] + bv.z; v.w = acc[i][3] + bv.w;
            if (do_relu) {
                v.x = fmaxf(v.x, 0.f); v.y = fmaxf(v.y, 0.f);
                v.z = fmaxf(v.z, 0.f); v.w = fmaxf(v.w, 0.f);
            }
            *(float4*)(C + (long)b * sC + (long)row * 1024 + col) = v;
        }
    }
}

// ------------- fused pair MLP: h1=relu(U[x]+V[y]+b1); h2=relu(h1@W2+b2); -----
// ------------- w=h2@W3+b3; A[x,y]=sigmoid(w).  grid (63, B), 256 threads -----
__global__ __launch_bounds__(256) void pair_mlp(
    const float* __restrict__ U, const float* __restrict__ V,
    const float* __restrict__ b1, const float* __restrict__ W2,
    const float* __restrict__ b2, const float* __restrict__ W3,
    const float* __restrict__ b3, float* __restrict__ Aout)
{
    __shared__ __align__(16) float W2s[16 * 512];   // 32 KB k-slab of W2
    __shared__ float h1s[16 * 16];                  // [pair][k]
    __shared__ float wsum2[16][2];

    const int b  = blockIdx.y;
    const int t  = threadIdx.x;
    const int tx = t & 63;      // col lane: cols tx + 64*j
    const int py = t >> 6;      // pair group: pairs 4*py..4*py+3

    // loader role for h1 tile: pair lp, k-offset lk
    const int lp = t >> 4, lk = t & 15;
    int mL = blockIdx.x * 16 + lp;
    int xL = mL / 63; int rL = mL - 63 * xL; int yL = rL + (rL >= xL ? 1 : 0);
    const float* Urow = U + ((long)(b * 64 + xL)) * 1024;
    const float* Vrow = V + ((long)(b * 64 + yL)) * 1024;

    float acc[4][8];
#pragma unroll
    for (int i = 0; i < 4; i++)
#pragma unroll
        for (int j = 0; j < 8; j++) acc[i][j] = 0.f;

    for (int k0 = 0; k0 < REP; k0 += 16) {
        // h1 tile: coalesced per row (16 consecutive k)
        h1s[lp * 16 + lk] = fmaxf(Urow[k0 + lk] + Vrow[k0 + lk] + b1[k0 + lk], 0.f);
        // W2 k-slab [k0..k0+15][0..511] is contiguous: 8192 floats from W2 + k0*512
#pragma unroll
        for (int i = 0; i < 8; i++) {
            int f = t + (i << 8);   // float4 index 0..2047
            *(float4*)&W2s[4 * f] = *(const float4*)(W2 + (long)k0 * 512 + 4 * f);
        }
        __syncthreads();
#pragma unroll
        for (int kk = 0; kk < 16; kk++) {
            float h0 = h1s[(4 * py + 0) * 16 + kk];
            float h1 = h1s[(4 * py + 1) * 16 + kk];
            float h2 = h1s[(4 * py + 2) * 16 + kk];
            float h3 = h1s[(4 * py + 3) * 16 + kk];
#pragma unroll
            for (int j = 0; j < 8; j++) {
                float wv = W2s[kk * 512 + tx + 64 * j];
                acc[0][j] += h0 * wv; acc[1][j] += h1 * wv;
                acc[2][j] += h2 * wv; acc[3][j] += h3 * wv;
            }
        }
        __syncthreads();
    }

    // epilogue: h2 = relu(acc + b2), partial w = h2 @ W3
    float part[4] = {0.f, 0.f, 0.f, 0.f};
#pragma unroll
    for (int j = 0; j < 8; j++) {
        int col = tx + 64 * j;
        float b2v = b2[col];
        float w3v = W3[col];
#pragma unroll
        for (int i = 0; i < 4; i++) {
            float h2v = fmaxf(acc[i][j] + b2v, 0.f);
            part[i] += h2v * w3v;
        }
    }
    // deterministic reduction: in-warp shfl, then combine the 2 warps per group
#pragma unroll
    for (int i = 0; i < 4; i++) {
        float v = part[i];
#pragma unroll
        for (int off = 16; off; off >>= 1) v += __shfl_xor_sync(0xffffffffu, v, off);
        if ((t & 31) == 0) wsum2[4 * py + i][(t >> 5) & 1] = v;
    }
    __syncthreads();
    if (t < 16) {
        int m = blockIdx.x * 16 + t;
        int x = m / 63; int r = m - 63 * x; int y = r + (r >= x ? 1 : 0);
        float w = wsum2[t][0] + wsum2[t][1] + b3[0];
        Aout[(b * 16 + x) * 64 + y] = 1.f / (1.f + expf(-w));
    }
}

// ---------------- msg_h = A @ O : [16,64]@[64,1024] per batch ----------------
__global__ __launch_bounds__(256) void msg_h_k(
    const float* __restrict__ Ag, const float* __restrict__ O, float* __restrict__ mh)
{
    __shared__ float As[NH * NN];
    const int b = blockIdx.y, t = threadIdx.x;
#pragma unroll
    for (int i = 0; i < 4; i++) As[t + 256 * i] = Ag[b * NH * NN + t + 256 * i];
    __syncthreads();
    const int j = blockIdx.x * 256 + t;
    float acc[NH];
#pragma unroll
    for (int x = 0; x < NH; x++) acc[x] = 0.f;
    for (int n = 0; n < NN; n++) {
        float o = O[((long)(b * NN + n)) * 1024 + j];
#pragma unroll
        for (int x = 0; x < NH; x++) acc[x] += As[x * NN + n] * o;
    }
#pragma unroll
    for (int x = 0; x < NH; x++) mh[((long)(b * NH + x)) * 1024 + j] = acc[x];
}

// ---------------- msg_o = A^T @ S : [64,16]@[16,1024] per batch --------------
__global__ __launch_bounds__(256) void msg_o_k(
    const float* __restrict__ Ag, const float* __restrict__ Sm, float* __restrict__ mo)
{
    __shared__ float As[NH * NN];
    const int b = blockIdx.y, t = threadIdx.x;
#pragma unroll
    for (int i = 0; i < 4; i++) As[t + 256 * i] = Ag[b * NH * NN + t + 256 * i];
    __syncthreads();
    const int j = blockIdx.x * 256 + t;
    float s[NH];
#pragma unroll
    for (int x = 0; x < NH; x++) s[x] = Sm[((long)(b * NH + x)) * 1024 + j];
    for (int n = 0; n < NN; n++) {
        float acc = 0.f;
#pragma unroll
        for (int x = 0; x < NH; x++) acc += As[x * NN + n] * s[x];
        mo[((long)(b * NN + n)) * 1024 + j] = acc;
    }
}

// ---------------- output assembly -------------------------------------------
__device__ __forceinline__ float lis_f(float s) {
    return 8.3f / (1.f + expf(12.f - 10.f * s));
}

__global__ __launch_bounds__(128) void out_kernel(
    const float* __restrict__ enc, const float* __restrict__ Ag,
    const float* __restrict__ coords, const int* __restrict__ labels,
    const float* __restrict__ scores, float* __restrict__ out)
{
    const int b = blockIdx.y, m = blockIdx.x, t = threadIdx.x;
    const int x = m / 63; const int r = m - 63 * x; const int y = r + (r >= x ? 1 : 0);
    const long row = (long)b * MM + m;

    const float4* ex = (const float4*)(enc + ((long)(b * NN + x)) * RR);
    const float4* ey = (const float4*)(enc + ((long)(b * NN + y)) * RR);
    float4* po = (float4*)(out + row * 2048);
#pragma unroll
    for (int i = 0; i < 4; i++) {
        int q = t + (i << 7);   // 0..511
        po[q] = (q < 256) ? ex[q] : ey[q - 256];
    }
    if (t < 4)        out[OFF_BH + row * 4 + t]       = coords[(b * NN + x) * 4 + t];
    else if (t < 8)   out[OFF_BO + row * 4 + (t - 4)] = coords[(b * NN + y) * 4 + (t - 4)];

    const int lbl = labels[b * NN + y];
    const float val = Ag[(b * NH + x) * NN + y] *
                      lis_f(scores[b * NN + x]) * lis_f(scores[b * NN + y]);
    for (int c = t; c < NCLS; c += 128)
        out[OFF_PR + row * (long)NCLS + c] = (c == lbl) ? val : 0.f;
}

// ---------------- host orchestration ----------------------------------------
extern "C" void kernel_launch(void* const* d_in, const int* in_sizes, int n_in,
                              void* d_out, int out_size)
{
    const float* box_features = (const float*)d_in[0];
    const float* box_coords   = (const float*)d_in[1];
    const int*   box_labels   = (const int*)  d_in[2];
    const float* box_scores   = (const float*)d_in[3];
    const float* W1  = (const float*)d_in[4];
    const float* b1  = (const float*)d_in[5];
    const float* W2  = (const float*)d_in[6];
    const float* b2  = (const float*)d_in[7];
    const float* W3  = (const float*)d_in[8];
    const float* b3  = (const float*)d_in[9];
    const float* Ws  = (const float*)d_in[10];
    const float* bs  = (const float*)d_in[11];
    const float* Wo  = (const float*)d_in[12];
    const float* bo  = (const float*)d_in[13];
    const float* Wsu = (const float*)d_in[14];
    const float* Wou = (const float*)d_in[15];
    float* out = (float*)d_out;

    float *encA, *encB, *U, *V, *O, *mh, *eh, *Sb, *mo, *Ag;
    cudaGetSymbolAddress((void**)&encA, g_encA);
    cudaGetSymbolAddress((void**)&encB, g_encB);
    cudaGetSymbolAddress((void**)&U,    g_U);
    cudaGetSymbolAddress((void**)&V,    g_V);
    cudaGetSymbolAddress((void**)&O,    g_O);
    cudaGetSymbolAddress((void**)&mh,   g_mh);
    cudaGetSymbolAddress((void**)&eh,   g_eh);
    cudaGetSymbolAddress((void**)&Sb,   g_S);
    cudaGetSymbolAddress((void**)&mo,   g_mo);
    cudaGetSymbolAddress((void**)&Ag,   g_A);

    cudaMemcpyAsync(encA, box_features, (size_t)BB * NN * RR * 4,
                    cudaMemcpyDeviceToDevice, 0);
    cudaMemsetAsync(Ag, 0, (size_t)BB * NH * NN * 4, 0);

    const long sEnc = (long)NN * RR;   // 64*1024
    const long sH   = (long)NH * RR;   // 16*1024
    dim3 gg(16, 1, BB);

    for (int it = 0; it < 2; it++) {
        float* encIn  = (it == 0) ? encA : encB;
        float* encOut = (it == 0) ? encB : encA;

        // U = enc @ W1[:1024], V = enc @ W1[1024:]
        gemm64<<<gg, 256>>>(encIn, 1024, (const float*)0, sEnc, 0,
                            W1,               (const float*)0, U, sEnc, 64, 1024, 0);
        gemm64<<<gg, 256>>>(encIn, 1024, (const float*)0, sEnc, 0,
                            W1 + 1024 * 1024, (const float*)0, V, sEnc, 64, 1024, 0);
        // A = sigmoid(pair MLP)
        pair_mlp<<<dim3(63, BB), 256>>>(U, V, b1, W2, b2, W3, b3, Ag);
        // O = relu(enc @ Wo + bo)
        gemm64<<<gg, 256>>>(encIn, 1024, (const float*)0, sEnc, 0,
                            Wo, bo, O, sEnc, 64, 1024, 1);
        // msg_h = A @ O
        msg_h_k<<<dim3(4, BB), 256>>>(Ag, O, mh);
        // enc_h = concat(enc[:16], msg_h) @ Wsu
        gemm64<<<gg, 256>>>(encIn, 1024, mh, sEnc, sH,
                            Wsu, (const float*)0, eh, sH, 16, 2048, 0);
        // enc[:16] = enc_h
        cudaMemcpy2DAsync(encIn, (size_t)sEnc * 4, eh, (size_t)sH * 4,
                          (size_t)sH * 4, BB, cudaMemcpyDeviceToDevice, 0);
        // S = relu(enc_h @ Ws + bs)
        gemm64<<<gg, 256>>>(eh, 1024, (const float*)0, sH, 0,
                            Ws, bs, Sb, sH, 16, 1024, 1);
        // msg_o = A^T @ S
        msg_o_k<<<dim3(4, BB), 256>>>(Ag, Sb, mo);
        // encOut = concat(enc, msg_o) @ Wou
        gemm64<<<gg, 256>>>(encIn, 1024, mo, sEnc, sEnc,
                            Wou, (const float*)0, encOut, sEnc, 64, 2048, 0);
    }

    // final enc is in encA after iter 1
    out_kernel<<<dim3(MM, BB), 128>>>(encA, Ag, box_coords, box_labels,
                                      box_scores, out);
    (void)in_sizes; (void)n_in; (void)out_size;
}

// round 2
// speedup vs baseline: 1.9497x; 1.9497x over previous
#include <cuda_runtime.h>
#include <math.h>
#include <stdint.h>

// Problem constants
#define BB   32
#define NN   64
#define NH   16
#define RR   1024
#define REP  1024
#define MM   1008
#define NCLS 117

// Output layout offsets (floats)
#define OFF_BH  66060288L
#define OFF_BO  66189312L
#define OFF_PR  66318336L

// ---------------- scratch (device globals; no allocation allowed) ------------
__device__ float g_encA[BB * NN * RR];
__device__ float g_encB[BB * NN * RR];
__device__ float g_U [BB * NN * REP];
__device__ float g_V [BB * NN * REP];
__device__ float g_O [BB * NN * REP];
__device__ float g_mh[BB * NH * REP];
__device__ float g_eh[BB * NH * RR];
__device__ float g_S [BB * NH * REP];
__device__ float g_mo[BB * NN * REP];
__device__ float g_A [BB * NH * NN];

// ---------------- tf32 mma helpers ------------------------------------------
__device__ __forceinline__ void mma8(float* c, const uint32_t* a, const uint32_t* b)
{
    asm volatile(
        "mma.sync.aligned.m16n8k8.row.col.f32.tf32.tf32.f32 "
        "{%0,%1,%2,%3}, {%4,%5,%6,%7}, {%8,%9}, {%0,%1,%2,%3};\n"
        : "+f"(c[0]), "+f"(c[1]), "+f"(c[2]), "+f"(c[3])
        : "r"(a[0]), "r"(a[1]), "r"(a[2]), "r"(a[3]), "r"(b[0]), "r"(b[1]));
}

// split x into hi (tf32) + lo (tf32), hi+lo ~= x to ~2^-22
__device__ __forceinline__ void split2(float x, uint32_t& hi, uint32_t& lo)
{
    uint32_t xb = __float_as_uint(x);
    uint32_t h  = xb & 0xffffe000u;
    hi = h;
    float l = x - __uint_as_float(h);
    lo = __float_as_uint(l) & 0xffffe000u;
}

// ---------------- generic batched GEMM (3xTF32): C = act(A @ W + bias) -------
// A rows are mapped: flat row r -> (b = r>>lrpb, n = r&mask); A may be a
// K-concat of A1 [.,K1] and A2 [.,Ktot-K1]. W row-major [Ktot,1024].
// C flat [Mtot,1024]. grid: (8 n-chunks, Mtot/64). 256 threads.
__global__ __launch_bounds__(256, 2) void gemm_tf32(
    const float* __restrict__ A1, int lrpb, long sA1, int K1,
    const float* __restrict__ A2, long sA2,
    const float* __restrict__ W, const float* __restrict__ bias,
    float* __restrict__ C, int Ktot, int do_relu)
{
    __shared__ __align__(16) float As[64][36];
    __shared__ __align__(16) float Bs[32][136];

    const int t    = threadIdx.x;
    const int lane = t & 31, warp = t >> 5;
    const int gid  = lane >> 2, tig = lane & 3;
    const int wm   = warp >> 2, wn = warp & 3;       // 2 x 4 warp grid
    const int m0   = wm * 32, n0w = wn * 32;
    const long bn0 = (long)blockIdx.x * 128;
    const int bm0  = blockIdx.y * 64;
    const int K2   = Ktot - K1;
    const int rmask = (1 << lrpb) - 1;

    const int lrow = t >> 3;            // + 32*i
    const int lk4  = (t & 7) * 4;
    const float* p1[2];
    const float* p2[2];
#pragma unroll
    for (int i = 0; i < 2; i++) {
        int grow = bm0 + lrow + 32 * i;
        int b = grow >> lrpb, n = grow & rmask;
        p1[i] = A1 + (long)b * sA1 + (long)n * K1;
        p2[i] = A2 ? (A2 + (long)b * sA2 + (long)n * K2) : p1[i];
    }

    float c[2][4][4];
#pragma unroll
    for (int mt = 0; mt < 2; mt++)
#pragma unroll
        for (int nt = 0; nt < 4; nt++)
#pragma unroll
            for (int e = 0; e < 4; e++) c[mt][nt][e] = 0.f;

    for (int k0 = 0; k0 < Ktot; k0 += 32) {
#pragma unroll
        for (int i = 0; i < 2; i++) {
            const float* src = (k0 < K1) ? (p1[i] + k0 + lk4)
                                         : (p2[i] + (k0 - K1) + lk4);
            *(float4*)&As[lrow + 32 * i][lk4] = *(const float4*)src;
        }
#pragma unroll
        for (int i = 0; i < 4; i++) {
            int f = t + i * 256;
            int kk = f >> 5, n4 = (f & 31) * 4;
            *(float4*)&Bs[kk][n4] =
                *(const float4*)(W + (long)(k0 + kk) * 1024 + bn0 + n4);
        }
        __syncthreads();

#pragma unroll
        for (int k8 = 0; k8 < 4; k8++) {
            const int kb = k8 * 8;
            uint32_t ah[2][4], al[2][4];
#pragma unroll
            for (int mt = 0; mt < 2; mt++) {
                int r = m0 + mt * 16 + gid;
                split2(As[r][kb + tig],         ah[mt][0], al[mt][0]);
                split2(As[r + 8][kb + tig],     ah[mt][1], al[mt][1]);
                split2(As[r][kb + tig + 4],     ah[mt][2], al[mt][2]);
                split2(As[r + 8][kb + tig + 4], ah[mt][3], al[mt][3]);
            }
#pragma unroll
            for (int nt = 0; nt < 4; nt++) {
                uint32_t bh[2], bl[2];
                int cn = n0w + nt * 8 + gid;
                split2(Bs[kb + tig][cn],     bh[0], bl[0]);
                split2(Bs[kb + tig + 4][cn], bh[1], bl[1]);
#pragma unroll
                for (int mt = 0; mt < 2; mt++) {
                    mma8(c[mt][nt], ah[mt], bh);
                    mma8(c[mt][nt], ah[mt], bl);
                    mma8(c[mt][nt], al[mt], bh);
                }
            }
        }
        __syncthreads();
    }

#pragma unroll
    for (int mt = 0; mt < 2; mt++) {
#pragma unroll
        for (int nt = 0; nt < 4; nt++) {
            long col = bn0 + n0w + nt * 8 + 2 * tig;
            float b0v = 0.f, b1v = 0.f;
            if (bias) { b0v = bias[col]; b1v = bias[col + 1]; }
            int r = bm0 + m0 + mt * 16 + gid;
            float v0 = c[mt][nt][0] + b0v, v1 = c[mt][nt][1] + b1v;
            float v2 = c[mt][nt][2] + b0v, v3 = c[mt][nt][3] + b1v;
            if (do_relu) {
                v0 = fmaxf(v0, 0.f); v1 = fmaxf(v1, 0.f);
                v2 = fmaxf(v2, 0.f); v3 = fmaxf(v3, 0.f);
            }
            *(float2*)&C[(long)r * 1024 + col]       = make_float2(v0, v1);
            *(float2*)&C[(long)(r + 8) * 1024 + col] = make_float2(v2, v3);
        }
    }
}

// ------------- fused pair MLP (3xTF32 mma): A[x,y] = sigmoid(MLP(pair)) ------
// h1 = relu(U[x]+V[y]+b1) built on the fly. Layer2 (K=1024 -> 512) via mma,
// layer3 + sigmoid fused. BM=32 pairs, BN=512 (full), BK=32. 256 threads.
// grid: (32 m-blocks, 32 images). Dynamic smem.
#define PAIR_SMEM_BYTES ((32 * 520 + 32 * 36 + 32 * 8) * 4)

__global__ __launch_bounds__(256, 2) void pair_mlp_mma(
    const float* __restrict__ U, const float* __restrict__ V,
    const float* __restrict__ b1, const float* __restrict__ W2,
    const float* __restrict__ b2, const float* __restrict__ W3,
    const float* __restrict__ b3, float* __restrict__ Aout)
{
    extern __shared__ __align__(16) float smp[];
    float* Bs    = smp;                    // [32][520]
    float* h1s   = smp + 32 * 520;         // [32][36]
    float* wpart = smp + 32 * 520 + 32 * 36; // [32][8]

    const int t    = threadIdx.x;
    const int lane = t & 31, warp = t >> 5;
    const int gid  = lane >> 2, tig = lane & 3;
    const int n0w  = warp * 64;            // 8 warps x 64 cols
    const int bi   = blockIdx.y;

    // h1 loader role: one float4 per thread per k-slab
    const int p  = t >> 3;
    const int kq = (t & 7) * 4;
    const int mld = blockIdx.x * 32 + p;
    const int validLd = (mld < MM);
    int xl = mld / 63; int rl = mld - 63 * xl; int yl = rl + (rl >= xl ? 1 : 0);
    if (!validLd) { xl = 0; yl = 0; }
    const float* Urow = U + ((long)(bi * 64 + xl)) * 1024;
    const float* Vrow = V + ((long)(bi * 64 + yl)) * 1024;

    float c[2][8][4];
#pragma unroll
    for (int mt = 0; mt < 2; mt++)
#pragma unroll
        for (int nt = 0; nt < 8; nt++)
#pragma unroll
            for (int e = 0; e < 4; e++) c[mt][nt][e] = 0.f;

    for (int k0 = 0; k0 < REP; k0 += 32) {
        // h1 tile
        float4 u4 = *(const float4*)(Urow + k0 + kq);
        float4 v4 = *(const float4*)(Vrow + k0 + kq);
        float4 bb = *(const float4*)(b1 + k0 + kq);
        float4 h;
        h.x = fmaxf(u4.x + v4.x + bb.x, 0.f);
        h.y = fmaxf(u4.y + v4.y + bb.y, 0.f);
        h.z = fmaxf(u4.z + v4.z + bb.z, 0.f);
        h.w = fmaxf(u4.w + v4.w + bb.w, 0.f);
        if (!validLd) h = make_float4(0.f, 0.f, 0.f, 0.f);
        *(float4*)&h1s[p * 36 + kq] = h;

        // W2 slab [32][512]
#pragma unroll
        for (int i = 0; i < 16; i++) {
            int f = t + i * 256;
            int kk = f >> 7, n4 = (f & 127) * 4;
            *(float4*)&Bs[kk * 520 + n4] =
                *(const float4*)(W2 + (long)(k0 + kk) * 512 + n4);
        }
        __syncthreads();

#pragma unroll
        for (int k8 = 0; k8 < 4; k8++) {
            const int kb = k8 * 8;
            uint32_t ah[2][4], al[2][4];
#pragma unroll
            for (int mt = 0; mt < 2; mt++) {
                int r = mt * 16 + gid;
                split2(h1s[r * 36 + kb + tig],           ah[mt][0], al[mt][0]);
                split2(h1s[(r + 8) * 36 + kb + tig],     ah[mt][1], al[mt][1]);
                split2(h1s[r * 36 + kb + tig + 4],       ah[mt][2], al[mt][2]);
                split2(h1s[(r + 8) * 36 + kb + tig + 4], ah[mt][3], al[mt][3]);
            }
#pragma unroll
            for (int nt = 0; nt < 8; nt++) {
                uint32_t bh[2], bl[2];
                int cn = n0w + nt * 8 + gid;
                split2(Bs[(kb + tig) * 520 + cn],     bh[0], bl[0]);
                split2(Bs[(kb + tig + 4) * 520 + cn], bh[1], bl[1]);
#pragma unroll
                for (int mt = 0; mt < 2; mt++) {
                    mma8(c[mt][nt], ah[mt], bh);
                    mma8(c[mt][nt], ah[mt], bl);
                    mma8(c[mt][nt], al[mt], bh);
                }
            }
        }
        __syncthreads();
    }

    // epilogue: h2 = relu(c + b2); row partial w += h2 * W3
    float rp[4] = {0.f, 0.f, 0.f, 0.f};
#pragma unroll
    for (int mt = 0; mt < 2; mt++) {
#pragma unroll
        for (int nt = 0; nt < 8; nt++) {
            int col = n0w + nt * 8 + 2 * tig;
            float b2a = b2[col],  b2b = b2[col + 1];
            float w3a = W3[col],  w3b = W3[col + 1];
            rp[2 * mt + 0] += fmaxf(c[mt][nt][0] + b2a, 0.f) * w3a
                            + fmaxf(c[mt][nt][1] + b2b, 0.f) * w3b;
            rp[2 * mt + 1] += fmaxf(c[mt][nt][2] + b2a, 0.f) * w3a
                            + fmaxf(c[mt][nt][3] + b2b, 0.f) * w3b;
        }
    }
#pragma unroll
    for (int e = 0; e < 4; e++) {
        float v = rp[e];
        v += __shfl_xor_sync(0xffffffffu, v, 1);
        v += __shfl_xor_sync(0xffffffffu, v, 2);
        if (tig == 0) wpart[(gid + 8 * e) * 8 + warp] = v;
    }
    __syncthreads();
    if (t < 32) {
        float s = b3[0];
#pragma unroll
        for (int w = 0; w < 8; w++) s += wpart[t * 8 + w];
        int m = blockIdx.x * 32 + t;
        if (m < MM) {
            int x = m / 63; int r = m - 63 * x; int y = r + (r >= x ? 1 : 0);
            Aout[(bi * 16 + x) * 64 + y] = 1.f / (1.f + expf(-s));
        }
    }
}

// ---------------- msg_h = A @ O : [16,64]@[64,1024] per batch ----------------
__global__ __launch_bounds__(256) void msg_h_k(
    const float* __restrict__ Ag, const float* __restrict__ O, float* __restrict__ mh)
{
    __shared__ float As[NH * NN];
    const int b = blockIdx.y, t = threadIdx.x;
#pragma unroll
    for (int i = 0; i < 4; i++) As[t + 256 * i] = Ag[b * NH * NN + t + 256 * i];
    __syncthreads();
    const int j = blockIdx.x * 256 + t;
    float acc[NH];
#pragma unroll
    for (int x = 0; x < NH; x++) acc[x] = 0.f;
    for (int n = 0; n < NN; n++) {
        float o = O[((long)(b * NN + n)) * 1024 + j];
#pragma unroll
        for (int x = 0; x < NH; x++) acc[x] += As[x * NN + n] * o;
    }
#pragma unroll
    for (int x = 0; x < NH; x++) mh[((long)(b * NH + x)) * 1024 + j] = acc[x];
}

// ---------------- msg_o = A^T @ S : [64,16]@[16,1024] per batch --------------
__global__ __launch_bounds__(256) void msg_o_k(
    const float* __restrict__ Ag, const float* __restrict__ Sm, float* __restrict__ mo)
{
    __shared__ float As[NH * NN];
    const int b = blockIdx.y, t = threadIdx.x;
#pragma unroll
    for (int i = 0; i < 4; i++) As[t + 256 * i] = Ag[b * NH * NN + t + 256 * i];
    __syncthreads();
    const int j = blockIdx.x * 256 + t;
    float s[NH];
#pragma unroll
    for (int x = 0; x < NH; x++) s[x] = Sm[((long)(b * NH + x)) * 1024 + j];
    for (int n = 0; n < NN; n++) {
        float acc = 0.f;
#pragma unroll
        for (int x = 0; x < NH; x++) acc += As[x * NN + n] * s[x];
        mo[((long)(b * NN + n)) * 1024 + j] = acc;
    }
}

// ---------------- output assembly -------------------------------------------
__device__ __forceinline__ float lis_f(float s) {
    return 8.3f / (1.f + expf(12.f - 10.f * s));
}

__global__ __launch_bounds__(128) void out_kernel(
    const float* __restrict__ enc, const float* __restrict__ Ag,
    const float* __restrict__ coords, const int* __restrict__ labels,
    const float* __restrict__ scores, float* __restrict__ out)
{
    const int b = blockIdx.y, m = blockIdx.x, t = threadIdx.x;
    const int x = m / 63; const int r = m - 63 * x; const int y = r + (r >= x ? 1 : 0);
    const long row = (long)b * MM + m;

    const float4* ex = (const float4*)(enc + ((long)(b * NN + x)) * RR);
    const float4* ey = (const float4*)(enc + ((long)(b * NN + y)) * RR);
    float4* po = (float4*)(out + row * 2048);
#pragma unroll
    for (int i = 0; i < 4; i++) {
        int q = t + (i << 7);   // 0..511
        po[q] = (q < 256) ? ex[q] : ey[q - 256];
    }
    if (t < 4)        out[OFF_BH + row * 4 + t]       = coords[(b * NN + x) * 4 + t];
    else if (t < 8)   out[OFF_BO + row * 4 + (t - 4)] = coords[(b * NN + y) * 4 + (t - 4)];

    const int lbl = labels[b * NN + y];
    const float val = Ag[(b * NH + x) * NN + y] *
                      lis_f(scores[b * NN + x]) * lis_f(scores[b * NN + y]);
    for (int c = t; c < NCLS; c += 128)
        out[OFF_PR + row * (long)NCLS + c] = (c == lbl) ? val : 0.f;
}

// ---------------- host orchestration ----------------------------------------
extern "C" void kernel_launch(void* const* d_in, const int* in_sizes, int n_in,
                              void* d_out, int out_size)
{
    const float* box_features = (const float*)d_in[0];
    const float* box_coords   = (const float*)d_in[1];
    const int*   box_labels   = (const int*)  d_in[2];
    const float* box_scores   = (const float*)d_in[3];
    const float* W1  = (const float*)d_in[4];
    const float* b1  = (const float*)d_in[5];
    const float* W2  = (const float*)d_in[6];
    const float* b2  = (const float*)d_in[7];
    const float* W3  = (const float*)d_in[8];
    const float* b3  = (const float*)d_in[9];
    const float* Ws  = (const float*)d_in[10];
    const float* bs  = (const float*)d_in[11];
    const float* Wo  = (const float*)d_in[12];
    const float* bo  = (const float*)d_in[13];
    const float* Wsu = (const float*)d_in[14];
    const float* Wou = (const float*)d_in[15];
    float* out = (float*)d_out;

    float *encA, *encB, *U, *V, *O, *mh, *eh, *Sb, *mo, *Ag;
    cudaGetSymbolAddress((void**)&encA, g_encA);
    cudaGetSymbolAddress((void**)&encB, g_encB);
    cudaGetSymbolAddress((void**)&U,    g_U);
    cudaGetSymbolAddress((void**)&V,    g_V);
    cudaGetSymbolAddress((void**)&O,    g_O);
    cudaGetSymbolAddress((void**)&mh,   g_mh);
    cudaGetSymbolAddress((void**)&eh,   g_eh);
    cudaGetSymbolAddress((void**)&Sb,   g_S);
    cudaGetSymbolAddress((void**)&mo,   g_mo);
    cudaGetSymbolAddress((void**)&Ag,   g_A);

    cudaFuncSetAttribute(pair_mlp_mma,
                         cudaFuncAttributeMaxDynamicSharedMemorySize,
                         PAIR_SMEM_BYTES);

    cudaMemcpyAsync(encA, box_features, (size_t)BB * NN * RR * 4,
                    cudaMemcpyDeviceToDevice, 0);
    cudaMemsetAsync(Ag, 0, (size_t)BB * NH * NN * 4, 0);

    const long sEnc = (long)NN * RR;   // 65536
    const long sH   = (long)NH * RR;   // 16384

    for (int it = 0; it < 2; it++) {
        float* encIn  = (it == 0) ? encA : encB;
        float* encOut = (it == 0) ? encB : encA;

        // U = enc @ W1[:1024],  V = enc @ W1[1024:]
        gemm_tf32<<<dim3(8, 32), 256>>>(encIn, 6, sEnc, 1024,
                                        (const float*)0, 0,
                                        W1, (const float*)0, U, 1024, 0);
        gemm_tf32<<<dim3(8, 32), 256>>>(encIn, 6, sEnc, 1024,
                                        (const float*)0, 0,
                                        W1 + 1024 * 1024, (const float*)0, V, 1024, 0);
        // A = sigmoid(pair MLP)
        pair_mlp_mma<<<dim3(32, BB), 256, PAIR_SMEM_BYTES>>>(
            U, V, b1, W2, b2, W3, b3, Ag);
        // O = relu(enc @ Wo + bo)
        gemm_tf32<<<dim3(8, 32), 256>>>(encIn, 6, sEnc, 1024,
                                        (const float*)0, 0,
                                        Wo, bo, O, 1024, 1);
        // msg_h = A @ O
        msg_h_k<<<dim3(4, BB), 256>>>(Ag, O, mh);
        // enc_h = concat(enc[:16], msg_h) @ Wsu
        gemm_tf32<<<dim3(8, 8), 256>>>(encIn, 4, sEnc, 1024,
                                       mh, sH,
                                       Wsu, (const float*)0, eh, 2048, 0);
        // enc[:16] = enc_h
        cudaMemcpy2DAsync(encIn, (size_t)sEnc * 4, eh, (size_t)sH * 4,
                          (size_t)sH * 4, BB, cudaMemcpyDeviceToDevice, 0);
        // S = relu(enc_h @ Ws + bs)
        gemm_tf32<<<dim3(8, 8), 256>>>(eh, 4, sH, 1024,
                                       (const float*)0, 0,
                                       Ws, bs, Sb, 1024, 1);
        // msg_o = A^T @ S
        msg_o_k<<<dim3(4, BB), 256>>>(Ag, Sb, mo);
        // encOut = concat(enc, msg_o) @ Wou
        gemm_tf32<<<dim3(8, 32), 256>>>(encIn, 6, sEnc, 1024,
                                        mo, sEnc,
                                        Wou, (const float*)0, encOut, 2048, 0);
    }

    // final enc is in encA after iter 1
    out_kernel<<<dim3(MM, BB), 128>>>(encA, Ag, box_coords, box_labels,
                                      box_scores, out);
    (void)in_sizes; (void)n_in; (void)out_size;
}